// round 6
// baseline (speedup 1.0000x reference)
#include <cuda_runtime.h>
#include <math.h>
#include <stdint.h>

#define Bb 8
#define Tt 8192
#define Ss 8192
#define Ff 64
#define Dd 64
#define EPSf 1e-9f
#define KVPAD 72
#define ASPLITS 16
#define AROWS (Ss/ASPLITS)   /* 512 rows per block in kv kernel */

// kv scratch [b][256][72]; cols 65..71 stay zero
__device__ __align__(16) float g_kv[Bb * 256 * KVPAD];

// ---------------------------------------------------------------------------
// helpers
// ---------------------------------------------------------------------------
__device__ __forceinline__ float ftf32(float x) {
    unsigned u;
    asm("cvt.rna.tf32.f32 %0, %1;" : "=r"(u) : "f"(x));
    return __uint_as_float(u);
}

__device__ __forceinline__ void mma8(float4& d,
                                     float a0, float a1, float a2, float a3,
                                     float b0, float b1) {
    asm("mma.sync.aligned.m16n8k8.row.col.f32.tf32.tf32.f32 "
        "{%0,%1,%2,%3},{%4,%5,%6,%7},{%8,%9},{%0,%1,%2,%3};"
        : "+f"(d.x), "+f"(d.y), "+f"(d.z), "+f"(d.w)
        : "r"(__float_as_uint(a0)), "r"(__float_as_uint(a1)),
          "r"(__float_as_uint(a2)), "r"(__float_as_uint(a3)),
          "r"(__float_as_uint(b0)), "r"(__float_as_uint(b1)));
}

__global__ void zero_kv_kernel() {
    int i = blockIdx.x * blockDim.x + threadIdx.x;
    if (i < Bb * 256 * KVPAD) g_kv[i] = 0.0f;
}

// ---------------------------------------------------------------------------
// smem layouts (float offsets)
// ---------------------------------------------------------------------------
// kernel A
#define A_KS   0        /* [64][68]  */
#define A_VS   4352     /* [64][72]  */
#define A_PHT  8960     /* [256][68] */
#define A_OHI  26368    /* [128][68] */
#define A_OLO  35072    /* [128][68] */
#define A_SSH  43776    /* [64]      */
#define A_PRT  43840    /* [512]     */
#define A_TOT  44352
// kernel B
#define B_PHIQ 0        /* [128][260], aliases Qs/Ohi/Olo during phase 1 */
#define B_QS   0        /* [128][68]  */
#define B_OHI  8704     /* [128][68]  */
#define B_OLO  17408    /* [128][68]  */
#define B_KVS  33280    /* [256][72]  */
#define B_SSH  51712    /* [128]; reused as 1/norm after epilogue  */
#define B_PRT  51840    /* [512]      */
#define B_TOT  52352

extern __shared__ float sm[];

// ---------------------------------------------------------------------------
// Kernel A: fused  K -> phi_k -> kv partial (split-K over S, atomics)
// block: 512 thr / 16 warps, 1 block/SM.  Per 64-row chunk:
//   XW[64x128] = K_chunk . Omega^T   (split tf32, warp owns 8 features)
//   PhT[256][64] = exp(+-XW - ss) + eps  (tf32, transposed)
//   acc[16 rows x 64] += PhT . V_chunk   (warp owns 16 kv rows)
// ---------------------------------------------------------------------------
__global__ __launch_bounds__(512, 1)
void kv_kernel(const float* __restrict__ key,
               const float* __restrict__ value,
               const float* __restrict__ omega) {
    const int b   = blockIdx.y;
    const int tid = threadIdx.x;
    const int w   = tid >> 5;          // 0..15
    const int ln  = tid & 31;
    const int gid = ln >> 2;
    const int tq  = ln & 3;

    float* Ks  = sm + A_KS;
    float* Vs  = sm + A_VS;
    float* PhT = sm + A_PHT;
    float* Ohi = sm + A_OHI;
    float* Olo = sm + A_OLO;
    float* ssh = sm + A_SSH;
    float* prt = sm + A_PRT;

    // omega -> hi/lo tf32 split in smem
    for (int i = tid; i < 128 * 64; i += 512) {
        int m = i >> 6, f = i & 63;
        float x  = omega[i];
        float hi = ftf32(x);
        Ohi[m * 68 + f] = hi;
        Olo[m * 68 + f] = ftf32(x - hi);
    }

    float4 acc[8];
    #pragma unroll
    for (int nt = 0; nt < 8; nt++) acc[nt] = make_float4(0.f, 0.f, 0.f, 0.f);
    float nrm0 = 0.f, nrm1 = 0.f;

    const int row0base = blockIdx.x * AROWS;

    for (int c = 0; c < AROWS / 64; c++) {
        __syncthreads();   // previous-iter PhT reads done before overwrite
        const int row0 = row0base + c * 64;

        // ---- load K chunk (+ssq partials) and V chunk (tf32-rounded) ----
        {
            int r = tid >> 3, j8 = tid & 7;      // 8 threads per row, 2 f4 each
            const float4* kg = (const float4*)(key + ((size_t)(b * Ss + row0 + r)) * Ff);
            float ps = 0.f;
            #pragma unroll
            for (int h = 0; h < 2; h++) {
                int j = j8 + h * 8;
                float4 x = kg[j];
                ps += x.x * x.x + x.y * x.y + x.z * x.z + x.w * x.w;
                ((float4*)(Ks + r * 68))[j] = x;
            }
            prt[tid] = ps;
            const float4* vg = (const float4*)(value + ((size_t)(b * Ss + row0 + r)) * Dd);
            #pragma unroll
            for (int h = 0; h < 2; h++) {
                int j = j8 + h * 8;
                float4 x = vg[j];
                float4 y;
                y.x = ftf32(x.x); y.y = ftf32(x.y); y.z = ftf32(x.z); y.w = ftf32(x.w);
                ((float4*)(Vs + r * 72))[j] = y;
            }
        }
        __syncthreads();
        if (tid < 64) {
            float s = 0.f;
            #pragma unroll
            for (int j = 0; j < 8; j++) s += prt[tid * 8 + j];
            ssh[tid] = 0.5f * s;
        }
        __syncthreads();

        // ---- XW = K . Omega^T  (warp w owns features [8w, 8w+8)) ----
        float4 xw[4];
        #pragma unroll
        for (int mt = 0; mt < 4; mt++) xw[mt] = make_float4(0.f, 0.f, 0.f, 0.f);

        const int mfeat = w * 8 + gid;
        for (int ks = 0; ks < 8; ks++) {
            int f0 = ks * 8 + tq;
            float bh0 = Ohi[mfeat * 68 + f0], bh1 = Ohi[mfeat * 68 + f0 + 4];
            float bl0 = Olo[mfeat * 68 + f0], bl1 = Olo[mfeat * 68 + f0 + 4];
            #pragma unroll
            for (int mt = 0; mt < 4; mt++) {
                int s = mt * 16 + gid;
                float a0 = Ks[s * 68 + f0],       a1 = Ks[(s + 8) * 68 + f0];
                float a2 = Ks[s * 68 + f0 + 4],   a3 = Ks[(s + 8) * 68 + f0 + 4];
                float h0 = ftf32(a0), h1 = ftf32(a1), h2 = ftf32(a2), h3 = ftf32(a3);
                float l0 = ftf32(a0 - h0), l1 = ftf32(a1 - h1);
                float l2 = ftf32(a2 - h2), l3 = ftf32(a3 - h3);
                mma8(xw[mt], h0, h1, h2, h3, bh0, bh1);
                mma8(xw[mt], l0, l1, l2, l3, bh0, bh1);
                mma8(xw[mt], h0, h1, h2, h3, bl0, bl1);
            }
        }

        // ---- phi epilogue: PhT[m][s] = tf32(exp(+-xw - ss) + eps) ----
        {
            int m0 = w * 8 + 2 * tq;
            #pragma unroll
            for (int mt = 0; mt < 4; mt++) {
                int s0 = mt * 16 + gid;
                float ssa = ssh[s0], ssb = ssh[s0 + 8];
                float4 v = xw[mt];
                PhT[m0 * 68 + s0]             = ftf32(__expf( v.x - ssa) + EPSf);
                PhT[(m0 + 1) * 68 + s0]       = ftf32(__expf( v.y - ssa) + EPSf);
                PhT[m0 * 68 + s0 + 8]         = ftf32(__expf( v.z - ssb) + EPSf);
                PhT[(m0 + 1) * 68 + s0 + 8]   = ftf32(__expf( v.w - ssb) + EPSf);
                PhT[(m0 + 128) * 68 + s0]     = ftf32(__expf(-v.x - ssa) + EPSf);
                PhT[(m0 + 129) * 68 + s0]     = ftf32(__expf(-v.y - ssa) + EPSf);
                PhT[(m0 + 128) * 68 + s0 + 8] = ftf32(__expf(-v.z - ssb) + EPSf);
                PhT[(m0 + 129) * 68 + s0 + 8] = ftf32(__expf(-v.w - ssb) + EPSf);
            }
        }
        __syncthreads();

        // ---- acc += PhT . V   (warp w owns kv rows [16w, 16w+16)) ----
        const int mr = 16 * w + gid;
        #pragma unroll 2
        for (int ks = 0; ks < 8; ks++) {
            int sc = ks * 8 + tq;
            float a0 = PhT[mr * 68 + sc];
            float a1 = PhT[(mr + 8) * 68 + sc];
            float a2 = PhT[mr * 68 + sc + 4];
            float a3 = PhT[(mr + 8) * 68 + sc + 4];
            // normalizer: each phi of this thread's rows appears exactly once
            nrm0 += a0 + a2;
            nrm1 += a1 + a3;
            #pragma unroll
            for (int nt = 0; nt < 8; nt++) {
                float b0 = Vs[sc * 72 + nt * 8 + gid];
                float b1 = Vs[(sc + 4) * 72 + nt * 8 + gid];
                mma8(acc[nt], a0, a1, a2, a3, b0, b1);
            }
        }
    }

    // ---- atomic reduce into g_kv ----
    float* gp = g_kv + (size_t)b * 256 * KVPAD;
    {
        int m0 = 16 * w + gid;
        #pragma unroll
        for (int nt = 0; nt < 8; nt++) {
            int d0 = nt * 8 + 2 * tq;
            atomicAdd(gp + m0 * KVPAD + d0,           acc[nt].x);
            atomicAdd(gp + m0 * KVPAD + d0 + 1,       acc[nt].y);
            atomicAdd(gp + (m0 + 8) * KVPAD + d0,     acc[nt].z);
            atomicAdd(gp + (m0 + 8) * KVPAD + d0 + 1, acc[nt].w);
        }
        float n0 = nrm0, n1 = nrm1;
        n0 += __shfl_xor_sync(0xffffffffu, n0, 1);
        n0 += __shfl_xor_sync(0xffffffffu, n0, 2);
        n1 += __shfl_xor_sync(0xffffffffu, n1, 1);
        n1 += __shfl_xor_sync(0xffffffffu, n1, 2);
        if (tq == 0) {
            atomicAdd(gp + m0 * KVPAD + 64,       n0);
            atomicAdd(gp + (m0 + 8) * KVPAD + 64, n1);
        }
    }
}

// ---------------------------------------------------------------------------
// Kernel B GEMM4 helper: warp processes n-tiles [NT0, NT0+NTN)
// ---------------------------------------------------------------------------
template<int NT0, int NTN>
__device__ __forceinline__ void gemm4_run(const float* PhiQ, const float* kvs,
                                          int tr, int tq, int gid,
                                          float4* oacc) {
    #pragma unroll 4
    for (int ks = 0; ks < 32; ks++) {
        int mc = ks * 8 + tq;
        float a0 = PhiQ[tr * 260 + mc];
        float a1 = PhiQ[(tr + 8) * 260 + mc];
        float a2 = PhiQ[tr * 260 + mc + 4];
        float a3 = PhiQ[(tr + 8) * 260 + mc + 4];
        #pragma unroll
        for (int i = 0; i < NTN; i++) {
            int nt = NT0 + i;
            float b0 = kvs[mc * KVPAD + nt * 8 + gid];
            float b1 = kvs[(mc + 4) * KVPAD + nt * 8 + gid];
            mma8(oacc[i], a0, a1, a2, a3, b0, b1);
        }
    }
}

// ---------------------------------------------------------------------------
// Kernel B: fused  Q -> phi_q -> out = (phi_q . kv) / normalizer
// block: 512 thr / 16 warps, 128 t-rows per block.
// GEMM1: warp owns 8 features.  GEMM4: warp pair splits 9 n-tiles 5/4.
// ---------------------------------------------------------------------------
__global__ __launch_bounds__(512, 1)
void out_kernel(const float* __restrict__ query,
                const float* __restrict__ omega,
                float* __restrict__ outp) {
    const int b   = blockIdx.y;
    const int t0  = blockIdx.x * 128;
    const int tid = threadIdx.x;
    const int w   = tid >> 5;          // 0..15
    const int ln  = tid & 31;
    const int gid = ln >> 2;
    const int tq  = ln & 3;

    float* PhiQ = sm + B_PHIQ;
    float* Qs   = sm + B_QS;
    float* Ohi  = sm + B_OHI;
    float* Olo  = sm + B_OLO;
    float* kvs  = sm + B_KVS;
    float* ssh  = sm + B_SSH;
    float* prt  = sm + B_PRT;

    // ---- phase-1 loads: Q tile, omega hi/lo, kv (tf32-rounded) ----
    {
        int r = tid >> 2, qd = tid & 3;    // 4 threads per row, 4 f4 each
        const float4* qg = (const float4*)(query + ((size_t)(b * Tt + t0 + r)) * Ff);
        float ps = 0.f;
        #pragma unroll
        for (int j = 0; j < 4; j++) {
            float4 x = qg[qd * 4 + j];
            ps += x.x * x.x + x.y * x.y + x.z * x.z + x.w * x.w;
            ((float4*)(Qs + r * 68))[qd * 4 + j] = x;
        }
        prt[tid] = ps;
    }
    for (int i = tid; i < 128 * 64; i += 512) {
        int m = i >> 6, f = i & 63;
        float x  = omega[i];
        float hi = ftf32(x);
        Ohi[m * 68 + f] = hi;
        Olo[m * 68 + f] = ftf32(x - hi);
    }
    {
        const float4* gk = (const float4*)(g_kv + (size_t)b * 256 * KVPAD);
        for (int i = tid; i < 256 * KVPAD / 4; i += 512) {
            float4 x = gk[i];
            float4 y;
            y.x = ftf32(x.x); y.y = ftf32(x.y); y.z = ftf32(x.z); y.w = ftf32(x.w);
            ((float4*)kvs)[i] = y;
        }
    }
    __syncthreads();
    if (tid < 128)
        ssh[tid] = 0.5f * (prt[4 * tid] + prt[4 * tid + 1] +
                           prt[4 * tid + 2] + prt[4 * tid + 3]);
    __syncthreads();

    // ---- XW = Q . Omega^T  (warp w owns features [8w, 8w+8)) ----
    float4 xw[8];
    #pragma unroll
    for (int mt = 0; mt < 8; mt++) xw[mt] = make_float4(0.f, 0.f, 0.f, 0.f);

    const int mfeat = w * 8 + gid;
    for (int ks = 0; ks < 8; ks++) {
        int f0 = ks * 8 + tq;
        float bh0 = Ohi[mfeat * 68 + f0], bh1 = Ohi[mfeat * 68 + f0 + 4];
        float bl0 = Olo[mfeat * 68 + f0], bl1 = Olo[mfeat * 68 + f0 + 4];
        #pragma unroll
        for (int mt = 0; mt < 8; mt++) {
            int t = mt * 16 + gid;
            float a0 = Qs[t * 68 + f0],       a1 = Qs[(t + 8) * 68 + f0];
            float a2 = Qs[t * 68 + f0 + 4],   a3 = Qs[(t + 8) * 68 + f0 + 4];
            float h0 = ftf32(a0), h1 = ftf32(a1), h2 = ftf32(a2), h3 = ftf32(a3);
            float l0 = ftf32(a0 - h0), l1 = ftf32(a1 - h1);
            float l2 = ftf32(a2 - h2), l3 = ftf32(a3 - h3);
            mma8(xw[mt], h0, h1, h2, h3, bh0, bh1);
            mma8(xw[mt], l0, l1, l2, l3, bh0, bh1);
            mma8(xw[mt], h0, h1, h2, h3, bl0, bl1);
        }
    }
    __syncthreads();   // all Qs/omega reads done; PhiQ may overwrite them now

    // ---- phi epilogue: PhiQ[t][m] = tf32(exp(+-xw - ss) + eps) ----
    {
        int m0 = w * 8 + 2 * tq;
        #pragma unroll
        for (int mt = 0; mt < 8; mt++) {
            int t = mt * 16 + gid;
            float ssa = ssh[t], ssb = ssh[t + 8];
            float4 v = xw[mt];
            PhiQ[t * 260 + m0]             = ftf32(__expf( v.x - ssa) + EPSf);
            PhiQ[t * 260 + m0 + 1]         = ftf32(__expf( v.y - ssa) + EPSf);
            PhiQ[(t + 8) * 260 + m0]       = ftf32(__expf( v.z - ssb) + EPSf);
            PhiQ[(t + 8) * 260 + m0 + 1]   = ftf32(__expf( v.w - ssb) + EPSf);
            PhiQ[t * 260 + m0 + 128]       = ftf32(__expf(-v.x - ssa) + EPSf);
            PhiQ[t * 260 + m0 + 129]       = ftf32(__expf(-v.y - ssa) + EPSf);
            PhiQ[(t + 8) * 260 + m0 + 128] = ftf32(__expf(-v.z - ssb) + EPSf);
            PhiQ[(t + 8) * 260 + m0 + 129] = ftf32(__expf(-v.w - ssb) + EPSf);
        }
    }
    __syncthreads();

    // ---- out = PhiQ . kv  (warp pair: wr owns t-rows [16wr,16wr+16),
    //      half 0 -> n-tiles 0..4, half 1 -> n-tiles 5..8 (incl. normalizer)) ----
    const int half = w >> 3;
    const int wr   = w & 7;
    const int tr   = 16 * wr + gid;

    float4 oacc[5];
    #pragma unroll
    for (int i = 0; i < 5; i++) oacc[i] = make_float4(0.f, 0.f, 0.f, 0.f);

    if (half == 0) gemm4_run<0, 5>(PhiQ, kvs, tr, tq, gid, oacc);
    else           gemm4_run<5, 4>(PhiQ, kvs, tr, tq, gid, oacc);

    // normalizer lives in n-tile 8 (half==1, i==3), col 64 -> lanes tq==0
    if (half == 1) {
        float n0 = __shfl_sync(0xffffffffu, oacc[3].x, ln & ~3);
        float n1 = __shfl_sync(0xffffffffu, oacc[3].z, ln & ~3);
        if (tq == 0) {
            ssh[tr]     = 1.0f / n0;   // ssh reused: 1/normalizer per t-row
            ssh[tr + 8] = 1.0f / n1;
        }
    }
    __syncthreads();

    float inv0 = ssh[tr];
    float inv1 = ssh[tr + 8];

    size_t orow = ((size_t)b * Tt + t0 + tr) * 64;
    if (half == 0) {
        #pragma unroll
        for (int i = 0; i < 5; i++) {
            int col = i * 8 + 2 * tq;
            *(float2*)(outp + orow + col) =
                make_float2(oacc[i].x * inv0, oacc[i].y * inv0);
            *(float2*)(outp + orow + 8 * 64 + col) =
                make_float2(oacc[i].z * inv1, oacc[i].w * inv1);
        }
    } else {
        #pragma unroll
        for (int i = 0; i < 3; i++) {
            int col = (5 + i) * 8 + 2 * tq;
            *(float2*)(outp + orow + col) =
                make_float2(oacc[i].x * inv0, oacc[i].y * inv0);
            *(float2*)(outp + orow + 8 * 64 + col) =
                make_float2(oacc[i].z * inv1, oacc[i].w * inv1);
        }
    }
}

// ---------------------------------------------------------------------------
// launch
// ---------------------------------------------------------------------------
extern "C" void kernel_launch(void* const* d_in, const int* in_sizes, int n_in,
                              void* d_out, int out_size) {
    const float* query = (const float*)d_in[0];
    const float* value = (const float*)d_in[1];
    const float* key   = (const float*)d_in[2];
    const float* omega = (const float*)d_in[3];
    float* out = (float*)d_out;

    cudaFuncSetAttribute(kv_kernel,  cudaFuncAttributeMaxDynamicSharedMemorySize,
                         A_TOT * (int)sizeof(float));
    cudaFuncSetAttribute(out_kernel, cudaFuncAttributeMaxDynamicSharedMemorySize,
                         B_TOT * (int)sizeof(float));

    zero_kv_kernel<<<(Bb * 256 * KVPAD + 511) / 512, 512>>>();
    kv_kernel<<<dim3(ASPLITS, Bb), 512, A_TOT * sizeof(float)>>>(key, value, omega);
    out_kernel<<<dim3(Tt / 128, Bb), 512, B_TOT * sizeof(float)>>>(query, omega, out);
}